// round 1
// baseline (speedup 1.0000x reference)
#include <cuda_runtime.h>

#define DD 128
#define RR 16
#define NN 50000

// Ping-pong layer buffers (25.6 MB each). __device__ globals: allocation-free.
__device__ float g_buf0[NN * DD];
__device__ float g_buf1[NN * DD];

__global__ void zero4_kernel(float4* __restrict__ p, int n) {
    int i = blockIdx.x * 256 + threadIdx.x;
    if (i < n) p[i] = make_float4(0.f, 0.f, 0.f, 0.f);
}

// One CTA = one relation r x one tile of 128 edges.
// X[e][k] = (relu?)(embIn[col[e]][k]) * val[e]   (gathered, L2-resident source)
// C = X @ T_r^T  (128x128x128 fp32, FFMA2 packed f32x2)
// out[row[e]][:] += C[e][:]  via red.global.add.v4.f32 (L2-resident target)
__global__ __launch_bounds__(256, 2)
void gcn_layer_kernel(const float* __restrict__ Tm,   // [R, D, D]
                      const float* __restrict__ ev,   // [R, E]
                      const int*   __restrict__ er,   // [R, E]
                      const int*   __restrict__ ec,   // [R, E]
                      const float* __restrict__ embIn,// [N, D]
                      float*       __restrict__ outAcc,// [N, D] pre-zeroed
                      int E, int doRelu)
{
    __shared__ float Xs[128][33];    // edge tile chunk [e][k], padded
    __shared__ float Ts[32][132];    // T^T chunk: Ts[k][i] = T[i][k0+k], padded
    __shared__ int   sCol[128];
    __shared__ int   sRow[128];
    __shared__ float sVal[128];

    const int tid = threadIdx.x;
    const int r   = blockIdx.y;
    const int e0  = blockIdx.x * 128;
    const float* Tr = Tm + r * DD * DD;

    if (tid < 128) {
        int e = e0 + tid;
        if (e < E) {
            sCol[tid] = ec[r * E + e];
            sRow[tid] = er[r * E + e];
            sVal[tid] = ev[r * E + e];
        } else {
            sCol[tid] = 0; sRow[tid] = 0; sVal[tid] = 0.f;  // val=0 -> contributes 0
        }
    }
    __syncthreads();

    // 8x8 register micro-tile per thread, packed as f32x2 pairs along i.
    unsigned long long acc[8][4];
    #pragma unroll
    for (int u = 0; u < 8; u++)
        #pragma unroll
        for (int v = 0; v < 4; v++) acc[u][v] = 0ull;

    const int tx = tid & 15;   // i-tile: columns tx*8 .. tx*8+7
    const int ty = tid >> 4;   // e-tile: rows    ty*8 .. ty*8+7

    for (int kc = 0; kc < 4; kc++) {
        const int k0 = kc * 32;

        // Gather X chunk [128 e][32 k]: lanes cover k -> 128B coalesced per edge (L2 hits)
        #pragma unroll
        for (int it = 0; it < 16; it++) {
            int idx = it * 256 + tid;
            int e = idx >> 5, k = idx & 31;
            float x = embIn[sCol[e] * DD + k0 + k];
            if (doRelu) x = fmaxf(x, 0.f);
            Xs[e][k] = x * sVal[e];
        }
        // Load T^T chunk: lanes cover k -> coalesced reads of T rows
        #pragma unroll
        for (int it = 0; it < 16; it++) {
            int idx = it * 256 + tid;
            int i = idx >> 5, kk = idx & 31;
            Ts[kk][i] = Tr[i * DD + k0 + kk];
        }
        __syncthreads();

        #pragma unroll
        for (int kk = 0; kk < 32; kk++) {
            // b: 16 consecutive T^T values = 8 f32x2 pairs, via two LDS.128 pairs
            const ulonglong2 b01 = *reinterpret_cast<const ulonglong2*>(&Ts[kk][tx * 8]);
            const ulonglong2 b23 = *reinterpret_cast<const ulonglong2*>(&Ts[kk][tx * 8 + 4]);
            const unsigned long long b0 = b01.x, b1 = b01.y, b2 = b23.x, b3 = b23.y;
            #pragma unroll
            for (int u = 0; u < 8; u++) {
                float av = Xs[ty * 8 + u][kk];      // broadcast LDS
                unsigned long long a2;
                asm("mov.b64 %0, {%1, %1};" : "=l"(a2) : "f"(av));
                asm("fma.rn.f32x2 %0, %1, %2, %0;" : "+l"(acc[u][0]) : "l"(a2), "l"(b0));
                asm("fma.rn.f32x2 %0, %1, %2, %0;" : "+l"(acc[u][1]) : "l"(a2), "l"(b1));
                asm("fma.rn.f32x2 %0, %1, %2, %0;" : "+l"(acc[u][2]) : "l"(a2), "l"(b2));
                asm("fma.rn.f32x2 %0, %1, %2, %0;" : "+l"(acc[u][3]) : "l"(a2), "l"(b3));
            }
        }
        __syncthreads();
    }

    // Scatter: each thread reds 8 rows x 8 consecutive cols (two 16B vector reds per row).
    // Warp footprint per red = 2 rows x 256B contiguous -> good sector utilization.
    #pragma unroll
    for (int u = 0; u < 8; u++) {
        int e = ty * 8 + u;
        float* dst = outAcc + sRow[e] * DD + tx * 8;
        float x0, x1, x2, x3, x4, x5, x6, x7;
        asm("mov.b64 {%0,%1}, %2;" : "=f"(x0), "=f"(x1) : "l"(acc[u][0]));
        asm("mov.b64 {%0,%1}, %2;" : "=f"(x2), "=f"(x3) : "l"(acc[u][1]));
        asm("mov.b64 {%0,%1}, %2;" : "=f"(x4), "=f"(x5) : "l"(acc[u][2]));
        asm("mov.b64 {%0,%1}, %2;" : "=f"(x6), "=f"(x7) : "l"(acc[u][3]));
        asm volatile("red.global.add.v4.f32 [%0], {%1,%2,%3,%4};"
                     :: "l"(dst),     "f"(x0), "f"(x1), "f"(x2), "f"(x3) : "memory");
        asm volatile("red.global.add.v4.f32 [%0], {%1,%2,%3,%4};"
                     :: "l"(dst + 4), "f"(x4), "f"(x5), "f"(x6), "f"(x7) : "memory");
    }
}

// Final: emb = relu(buf); out = emb / max(||emb||_2, 1e-12). One warp per row.
__global__ void norm_kernel(const float* __restrict__ in, float* __restrict__ out, int n) {
    int row  = blockIdx.x * 8 + (threadIdx.x >> 5);
    int lane = threadIdx.x & 31;
    if (row >= n) return;
    float4 v = *reinterpret_cast<const float4*>(in + row * DD + lane * 4);
    v.x = fmaxf(v.x, 0.f); v.y = fmaxf(v.y, 0.f);
    v.z = fmaxf(v.z, 0.f); v.w = fmaxf(v.w, 0.f);
    float s = v.x * v.x + v.y * v.y + v.z * v.z + v.w * v.w;
    #pragma unroll
    for (int o = 16; o; o >>= 1) s += __shfl_xor_sync(0xffffffffu, s, o);
    float sc = 1.f / fmaxf(sqrtf(s), 1e-12f);
    v.x *= sc; v.y *= sc; v.z *= sc; v.w *= sc;
    *reinterpret_cast<float4*>(out + row * DD + lane * 4) = v;
}

extern "C" void kernel_launch(void* const* d_in, const int* in_sizes, int n_in,
                              void* d_out, int out_size) {
    const float* ent = (const float*)d_in[0];   // [N, D]
    const float* Tm  = (const float*)d_in[1];   // [R, D, D]
    const float* ev  = (const float*)d_in[2];   // [R, E]
    const int*   er  = (const int*)d_in[3];     // [R, E]
    const int*   ec  = (const int*)d_in[4];     // [R, E]
    float* out = (float*)d_out;

    const int E  = in_sizes[2] / RR;
    const int Nn = in_sizes[0] / DD;

    float *buf0, *buf1;
    cudaGetSymbolAddress((void**)&buf0, g_buf0);
    cudaGetSymbolAddress((void**)&buf1, g_buf1);

    const int n4 = Nn * DD / 4;
    const int zb = (n4 + 255) / 256;
    dim3 lgrid((E + 127) / 128, RR);

    zero4_kernel<<<zb, 256>>>((float4*)buf0, n4);
    gcn_layer_kernel<<<lgrid, 256>>>(Tm, ev, er, ec, ent,  buf0, E, 0);
    zero4_kernel<<<zb, 256>>>((float4*)buf1, n4);
    gcn_layer_kernel<<<lgrid, 256>>>(Tm, ev, er, ec, buf0, buf1, E, 1);
    norm_kernel<<<(Nn + 7) / 8, 256>>>(buf1, out, Nn);
}

// round 4
// speedup vs baseline: 1.7466x; 1.7466x over previous
#include <cuda_runtime.h>
#include <cuda_bf16.h>
#include <cstdint>

#define DD 128
#define RR 16
#define NN 50000

// Static device scratch (allocation-free).
__device__ float g_out0[NN * DD];
__device__ float g_out1[NN * DD];
__device__ float g_Z[2 * NN * DD];                 // Z for a relation pair (L2-resident)
__device__ __nv_bfloat16 g_ehi[NN * DD];
__device__ __nv_bfloat16 g_elo[NN * DD];
__device__ __nv_bfloat16 g_Thi[RR * DD * DD];
__device__ __nv_bfloat16 g_Tlo[RR * DD * DD];

static __device__ __forceinline__ uint32_t smem_u32(const void* p) {
    uint32_t a;
    asm("{ .reg .u64 t; cvta.to.shared.u64 t, %1; cvt.u32.u64 %0, t; }" : "=r"(a) : "l"(p));
    return a;
}

static __device__ __forceinline__ void ldsm_x4(uint32_t* r, uint32_t addr) {
    asm volatile("ldmatrix.sync.aligned.m8n8.x4.shared.b16 {%0,%1,%2,%3}, [%4];"
                 : "=r"(r[0]), "=r"(r[1]), "=r"(r[2]), "=r"(r[3]) : "r"(addr));
}

static __device__ __forceinline__ void mma16816(float* d, const uint32_t* a,
                                                uint32_t b0, uint32_t b1) {
    asm volatile(
        "mma.sync.aligned.m16n8k16.row.col.f32.bf16.bf16.f32 "
        "{%0,%1,%2,%3}, {%4,%5,%6,%7}, {%8,%9}, {%0,%1,%2,%3};"
        : "+f"(d[0]), "+f"(d[1]), "+f"(d[2]), "+f"(d[3])
        : "r"(a[0]), "r"(a[1]), "r"(a[2]), "r"(a[3]), "r"(b0), "r"(b1));
}

// smem plane offsets (each 128x128 bf16 = 32 KB, 256B rows, 16B-chunk XOR swizzle)
#define P_AHI 0
#define P_ALO 32768
#define P_B   65536          // 4 planes: r0 hi, r0 lo, r1 hi, r1 lo
#define SMEM_SZ2 (65536 + 4 * 32768)

// ---------------- GEMM: Z[rel][n0..n0+127] = emb @ T_{r0+rel}^T, rel = 0,1 ----------------
// bf16 2-way split, 3 accumulating HMMA passes -> ~1e-5 relative accuracy.
__global__ void __launch_bounds__(256, 1)
gemm2_kernel(const __nv_bfloat16* __restrict__ Ahi, const __nv_bfloat16* __restrict__ Alo,
             const __nv_bfloat16* __restrict__ Thi, const __nv_bfloat16* __restrict__ Tlo,
             float* __restrict__ Z, int r0)
{
    extern __shared__ char sm[];
    const int tid = threadIdx.x;
    const int n0 = blockIdx.x * 128;

    // Load A hi/lo tile (rows n0..n0+127), guarded; swizzled stores.
    {
        const uint4* ah = (const uint4*)(Ahi + (size_t)n0 * DD);
        const uint4* al = (const uint4*)(Alo + (size_t)n0 * DD);
        #pragma unroll
        for (int i = tid; i < 2048; i += 256) {
            int row = i >> 4, c = i & 15;
            int off = row * 256 + ((c ^ (row & 7)) << 4);
            uint4 vh, vl;
            if (n0 + row < NN) { vh = ah[i]; vl = al[i]; }
            else { vh = make_uint4(0, 0, 0, 0); vl = vh; }
            *(uint4*)(sm + P_AHI + off) = vh;
            *(uint4*)(sm + P_ALO + off) = vl;
        }
    }
    // Load B planes: T_{r0} hi/lo, T_{r0+1} hi/lo.
    {
        const uint4* b0h = (const uint4*)(Thi + (size_t)r0 * DD * DD);
        const uint4* b0l = (const uint4*)(Tlo + (size_t)r0 * DD * DD);
        const uint4* b1h = (const uint4*)(Thi + (size_t)(r0 + 1) * DD * DD);
        const uint4* b1l = (const uint4*)(Tlo + (size_t)(r0 + 1) * DD * DD);
        #pragma unroll
        for (int i = tid; i < 2048; i += 256) {
            int row = i >> 4, c = i & 15;
            int off = row * 256 + ((c ^ (row & 7)) << 4);
            *(uint4*)(sm + P_B + off)          = b0h[i];
            *(uint4*)(sm + P_B + 32768 + off)  = b0l[i];
            *(uint4*)(sm + P_B + 65536 + off)  = b1h[i];
            *(uint4*)(sm + P_B + 98304 + off)  = b1l[i];
        }
    }
    __syncthreads();

    const int w = tid >> 5, l = tid & 31;
    const int m0w = (w & 3) * 32;        // warp's row offset within tile
    const int n0w = (w >> 2) * 64;       // warp's col offset

    // lane-constant ldmatrix pieces
    const int rA = l & 15;               // A: row-within-16
    const int hiA = l >> 4;              // A: chunk + 0/1
    const int rB = ((l >> 4) << 3) + (l & 7);  // B: row-within-16
    const int hiB = (l >> 3) & 1;        // B: chunk + 0/1

    const uint32_t smA = smem_u32(sm);

    #pragma unroll
    for (int rel = 0; rel < 2; rel++) {
        float d[2][8][4];
        #pragma unroll
        for (int mt = 0; mt < 2; mt++)
            #pragma unroll
            for (int nt = 0; nt < 8; nt++)
                #pragma unroll
                for (int v = 0; v < 4; v++) d[mt][nt][v] = 0.f;

        #pragma unroll
        for (int pass = 0; pass < 3; pass++) {
            // passes: Ahi*Bhi, Ahi*Blo, Alo*Bhi
            const uint32_t aBase = smA + (pass == 2 ? P_ALO : P_AHI);
            const uint32_t bBase = smA + P_B + rel * 65536 + (pass == 1 ? 32768 : 0);

            #pragma unroll
            for (int ks = 0; ks < 8; ks++) {
                uint32_t a[2][4];
                #pragma unroll
                for (int mt = 0; mt < 2; mt++) {
                    int rowA = m0w + 16 * mt + rA;
                    uint32_t addr = aBase + rowA * 256 +
                                    ((((ks << 1) + hiA) ^ (rowA & 7)) << 4);
                    ldsm_x4(a[mt], addr);
                }
                uint32_t b[4][4];
                #pragma unroll
                for (int ntp = 0; ntp < 4; ntp++) {
                    int rowB = n0w + 16 * ntp + rB;
                    uint32_t addr = bBase + rowB * 256 +
                                    ((((ks << 1) + hiB) ^ (rowB & 7)) << 4);
                    ldsm_x4(b[ntp], addr);
                }
                #pragma unroll
                for (int mt = 0; mt < 2; mt++)
                    #pragma unroll
                    for (int ntp = 0; ntp < 4; ntp++) {
                        mma16816(d[mt][2 * ntp],     a[mt], b[ntp][0], b[ntp][1]);
                        mma16816(d[mt][2 * ntp + 1], a[mt], b[ntp][2], b[ntp][3]);
                    }
            }
        }

        // Epilogue: C frag (c0,c1)->(row, col..col+1), (c2,c3)->(row+8, ...)
        #pragma unroll
        for (int mt = 0; mt < 2; mt++) {
            int row = n0 + m0w + 16 * mt + (l >> 2);
            float* zp0 = Z + ((size_t)rel * NN + row) * DD;
            float* zp1 = zp0 + 8 * DD;
            if (row < NN) {
                #pragma unroll
                for (int nt = 0; nt < 8; nt++) {
                    int col = n0w + 8 * nt + 2 * (l & 3);
                    *(float2*)(zp0 + col) = make_float2(d[mt][nt][0], d[mt][nt][1]);
                }
            }
            if (row + 8 < NN) {
                #pragma unroll
                for (int nt = 0; nt < 8; nt++) {
                    int col = n0w + 8 * nt + 2 * (l & 3);
                    *(float2*)(zp1 + col) = make_float2(d[mt][nt][2], d[mt][nt][3]);
                }
            }
        }
    }
}

// ---------------- scatter: out[row] += val * Z[rr][col]  (1 warp per edge) ----------------
__global__ void __launch_bounds__(128, 8)
scatter_kernel(const float* __restrict__ Z, const float* __restrict__ ev,
               const int* __restrict__ er, const int* __restrict__ ec,
               float* __restrict__ out, int E, int r0)
{
    int ge = blockIdx.x * 4 + (threadIdx.x >> 5);
    if (ge >= 2 * E) return;
    int lane = threadIdx.x & 31;
    int rr = ge / E;
    int e = ge - rr * E;
    int r = r0 + rr;
    int col = ec[r * E + e];
    int row = er[r * E + e];
    float val = ev[r * E + e];
    float4 v = *(const float4*)(Z + ((size_t)rr * NN + col) * DD + lane * 4);
    v.x *= val; v.y *= val; v.z *= val; v.w *= val;
    float* dst = out + (size_t)row * DD + lane * 4;
    asm volatile("red.global.add.v4.f32 [%0], {%1,%2,%3,%4};"
                 :: "l"(dst), "f"(v.x), "f"(v.y), "f"(v.z), "f"(v.w) : "memory");
}

// ---------------- split fp32 -> bf16 hi/lo (optionally relu) ----------------
__global__ void split_kernel(const float* __restrict__ in, __nv_bfloat16* __restrict__ hi,
                             __nv_bfloat16* __restrict__ lo, int n, int doRelu)
{
    int i = blockIdx.x * 256 + threadIdx.x;
    if (i >= n) return;
    float x = in[i];
    if (doRelu) x = fmaxf(x, 0.f);
    __nv_bfloat16 h = __float2bfloat16(x);
    hi[i] = h;
    lo[i] = __float2bfloat16(x - __bfloat162float(h));
}

__global__ void zero4_kernel(float4* __restrict__ p, int n) {
    int i = blockIdx.x * 256 + threadIdx.x;
    if (i < n) p[i] = make_float4(0.f, 0.f, 0.f, 0.f);
}

// Final: relu + L2 row-normalize. One warp per row.
__global__ void norm_kernel(const float* __restrict__ in, float* __restrict__ out, int n) {
    int row = blockIdx.x * 8 + (threadIdx.x >> 5);
    int lane = threadIdx.x & 31;
    if (row >= n) return;
    float4 v = *reinterpret_cast<const float4*>(in + (size_t)row * DD + lane * 4);
    v.x = fmaxf(v.x, 0.f); v.y = fmaxf(v.y, 0.f);
    v.z = fmaxf(v.z, 0.f); v.w = fmaxf(v.w, 0.f);
    float s = v.x * v.x + v.y * v.y + v.z * v.z + v.w * v.w;
    #pragma unroll
    for (int o = 16; o; o >>= 1) s += __shfl_xor_sync(0xffffffffu, s, o);
    float sc = 1.f / fmaxf(sqrtf(s), 1e-12f);
    v.x *= sc; v.y *= sc; v.z *= sc; v.w *= sc;
    *reinterpret_cast<float4*>(out + (size_t)row * DD + lane * 4) = v;
}

extern "C" void kernel_launch(void* const* d_in, const int* in_sizes, int n_in,
                              void* d_out, int out_size) {
    const float* ent = (const float*)d_in[0];   // [N, D]
    const float* Tm  = (const float*)d_in[1];   // [R, D, D]
    const float* ev  = (const float*)d_in[2];   // [R, E]
    const int*   er  = (const int*)d_in[3];     // [R, E]
    const int*   ec  = (const int*)d_in[4];     // [R, E]
    float* out = (float*)d_out;

    const int E = in_sizes[2] / RR;

    float *out0, *out1, *Z;
    __nv_bfloat16 *ehi, *elo, *Thi, *Tlo;
    cudaGetSymbolAddress((void**)&out0, g_out0);
    cudaGetSymbolAddress((void**)&out1, g_out1);
    cudaGetSymbolAddress((void**)&Z, g_Z);
    cudaGetSymbolAddress((void**)&ehi, g_ehi);
    cudaGetSymbolAddress((void**)&elo, g_elo);
    cudaGetSymbolAddress((void**)&Thi, g_Thi);
    cudaGetSymbolAddress((void**)&Tlo, g_Tlo);

    cudaFuncSetAttribute(gemm2_kernel, cudaFuncAttributeMaxDynamicSharedMemorySize, SMEM_SZ2);

    const int nE = NN * DD;                 // 6.4M
    const int nT = RR * DD * DD;
    const int rowTiles = (NN + 127) / 128;  // 391
    const int sgrid = (2 * E + 3) / 4;

    // Split relation matrices.
    split_kernel<<<(nT + 255) / 256, 256>>>(Tm, Thi, Tlo, nT, 0);

    // ---- layer 1 ----
    split_kernel<<<(nE + 255) / 256, 256>>>(ent, ehi, elo, nE, 0);
    zero4_kernel<<<(nE / 4 + 255) / 256, 256>>>((float4*)out0, nE / 4);
    for (int r0 = 0; r0 < RR; r0 += 2) {
        gemm2_kernel<<<rowTiles, 256, SMEM_SZ2>>>(ehi, elo, Thi, Tlo, Z, r0);
        scatter_kernel<<<sgrid, 128>>>(Z, ev, er, ec, out0, E, r0);
    }

    // ---- layer 2 ----
    split_kernel<<<(nE + 255) / 256, 256>>>(out0, ehi, elo, nE, 1);
    zero4_kernel<<<(nE / 4 + 255) / 256, 256>>>((float4*)out1, nE / 4);
    for (int r0 = 0; r0 < RR; r0 += 2) {
        gemm2_kernel<<<rowTiles, 256, SMEM_SZ2>>>(ehi, elo, Thi, Tlo, Z, r0);
        scatter_kernel<<<sgrid, 128>>>(Z, ev, er, ec, out1, E, r0);
    }

    norm_kernel<<<(NN + 7) / 8, 256>>>(out1, out, NN);
}

// round 5
// speedup vs baseline: 1.9537x; 1.1186x over previous
#include <cuda_runtime.h>
#include <cuda_bf16.h>
#include <cstdint>

#define DD 128
#define RR 16
#define NN 50000

// Static device scratch (allocation-free).
__device__ float g_out0[NN * DD];
__device__ float g_out1[NN * DD];
__device__ float g_Z[2 * NN * DD];                 // Z for a relation pair (L2-resident)
__device__ __nv_bfloat16 g_ehi[NN * DD];
__device__ __nv_bfloat16 g_elo[NN * DD];
__device__ __nv_bfloat16 g_Thi[RR * DD * DD];
__device__ __nv_bfloat16 g_Tlo[RR * DD * DD];

static __device__ __forceinline__ uint32_t smem_u32(const void* p) {
    uint32_t a;
    asm("{ .reg .u64 t; cvta.to.shared.u64 t, %1; cvt.u32.u64 %0, t; }" : "=r"(a) : "l"(p));
    return a;
}

static __device__ __forceinline__ void ldsm_x4(uint32_t* r, uint32_t addr) {
    asm volatile("ldmatrix.sync.aligned.m8n8.x4.shared.b16 {%0,%1,%2,%3}, [%4];"
                 : "=r"(r[0]), "=r"(r[1]), "=r"(r[2]), "=r"(r[3]) : "r"(addr));
}

static __device__ __forceinline__ void mma16816(float* d, const uint32_t* a,
                                                uint32_t b0, uint32_t b1) {
    asm volatile(
        "mma.sync.aligned.m16n8k16.row.col.f32.bf16.bf16.f32 "
        "{%0,%1,%2,%3}, {%4,%5,%6,%7}, {%8,%9}, {%0,%1,%2,%3};"
        : "+f"(d[0]), "+f"(d[1]), "+f"(d[2]), "+f"(d[3])
        : "r"(a[0]), "r"(a[1]), "r"(a[2]), "r"(a[3]), "r"(b0), "r"(b1));
}

static __device__ __forceinline__ void cpa16(uint32_t dst, const void* src, bool p) {
    asm volatile("cp.async.ca.shared.global [%0], [%1], 16, %2;"
                 :: "r"(dst), "l"(src), "r"(p ? 16 : 0) : "memory");
}

// smem plane offsets (each 128x128 bf16 = 32 KB, 256B rows, 16B-chunk XOR swizzle)
#define P_AHI 0
#define P_ALO 32768
#define P_B   65536          // 4 planes: r0 hi, r0 lo, r1 hi, r1 lo
#define SMEM_SZ2 (65536 + 4 * 32768)

// ---------------- GEMM: Z[rel][n0..n0+127] = emb @ T_{r0+rel}^T, rel = 0,1 ----------------
// bf16 2-way split: d += Ahi*Bhi + Ahi*Blo + Alo*Bhi (A-frags shared across passes).
__global__ void __launch_bounds__(256, 1)
gemm2_kernel(const __nv_bfloat16* __restrict__ Ahi, const __nv_bfloat16* __restrict__ Alo,
             const __nv_bfloat16* __restrict__ Thi, const __nv_bfloat16* __restrict__ Tlo,
             float* __restrict__ Z, int r0)
{
    extern __shared__ char sm[];
    const int tid = threadIdx.x;
    const int n0 = blockIdx.x * 128;
    const uint32_t sbase = smem_u32(sm);

    // Group 0: A hi/lo tile + B planes for rel 0 (cp.async, zero-fill OOB rows).
    {
        const uint4* ah = (const uint4*)(Ahi + (size_t)n0 * DD);
        const uint4* al = (const uint4*)(Alo + (size_t)n0 * DD);
        const uint4* b0h = (const uint4*)(Thi + (size_t)r0 * DD * DD);
        const uint4* b0l = (const uint4*)(Tlo + (size_t)r0 * DD * DD);
        #pragma unroll
        for (int i = tid; i < 2048; i += 256) {
            int row = i >> 4, c = i & 15;
            uint32_t off = row * 256 + ((c ^ (row & 7)) << 4);
            bool p = (n0 + row < NN);
            cpa16(sbase + P_AHI + off, ah + i, p);
            cpa16(sbase + P_ALO + off, al + i, p);
            cpa16(sbase + P_B + off, b0h + i, true);
            cpa16(sbase + P_B + 32768 + off, b0l + i, true);
        }
        asm volatile("cp.async.commit_group;" ::: "memory");
    }
    // Group 1: B planes for rel 1 (overlaps with rel-0 compute).
    {
        const uint4* b1h = (const uint4*)(Thi + (size_t)(r0 + 1) * DD * DD);
        const uint4* b1l = (const uint4*)(Tlo + (size_t)(r0 + 1) * DD * DD);
        #pragma unroll
        for (int i = tid; i < 2048; i += 256) {
            int row = i >> 4, c = i & 15;
            uint32_t off = row * 256 + ((c ^ (row & 7)) << 4);
            cpa16(sbase + P_B + 65536 + off, b1h + i, true);
            cpa16(sbase + P_B + 98304 + off, b1l + i, true);
        }
        asm volatile("cp.async.commit_group;" ::: "memory");
    }
    asm volatile("cp.async.wait_group 1;" ::: "memory");
    __syncthreads();

    const int w = tid >> 5, l = tid & 31;
    const int m0w = (w & 3) * 32;        // warp's row offset within tile
    const int n0w = (w >> 2) * 64;       // warp's col offset

    // lane-constant ldmatrix pieces
    const int rA = l & 15;               // A: row-within-16
    const int hiA = l >> 4;              // A: chunk + 0/1
    const int rB = ((l >> 4) << 3) + (l & 7);  // B: row-within-16
    const int hiB = (l >> 3) & 1;        // B: chunk + 0/1

    #pragma unroll 1
    for (int rel = 0; rel < 2; rel++) {
        float d[2][8][4];
        #pragma unroll
        for (int mt = 0; mt < 2; mt++)
            #pragma unroll
            for (int nt = 0; nt < 8; nt++)
                #pragma unroll
                for (int v = 0; v < 4; v++) d[mt][nt][v] = 0.f;

        const uint32_t aHiB = sbase + P_AHI;
        const uint32_t aLoB = sbase + P_ALO;
        const uint32_t bHiB = sbase + P_B + rel * 65536;
        const uint32_t bLoB = bHiB + 32768;

        #pragma unroll
        for (int ks = 0; ks < 8; ks++) {
            uint32_t ah2[2][4], al2[2][4];
            #pragma unroll
            for (int mt = 0; mt < 2; mt++) {
                int rowA = m0w + 16 * mt + rA;
                uint32_t co = ((((ks << 1) + hiA) ^ (rowA & 7)) << 4);
                ldsm_x4(ah2[mt], aHiB + rowA * 256 + co);
                ldsm_x4(al2[mt], aLoB + rowA * 256 + co);
            }
            uint32_t bh[4][4], bl[4][4];
            #pragma unroll
            for (int ntp = 0; ntp < 4; ntp++) {
                int rowB = n0w + 16 * ntp + rB;
                uint32_t co = ((((ks << 1) + hiB) ^ (rowB & 7)) << 4);
                ldsm_x4(bh[ntp], bHiB + rowB * 256 + co);
                ldsm_x4(bl[ntp], bLoB + rowB * 256 + co);
            }
            #pragma unroll
            for (int mt = 0; mt < 2; mt++)
                #pragma unroll
                for (int ntp = 0; ntp < 4; ntp++) {
                    mma16816(d[mt][2 * ntp],     ah2[mt], bh[ntp][0], bh[ntp][1]);
                    mma16816(d[mt][2 * ntp + 1], ah2[mt], bh[ntp][2], bh[ntp][3]);
                    mma16816(d[mt][2 * ntp],     ah2[mt], bl[ntp][0], bl[ntp][1]);
                    mma16816(d[mt][2 * ntp + 1], ah2[mt], bl[ntp][2], bl[ntp][3]);
                    mma16816(d[mt][2 * ntp],     al2[mt], bh[ntp][0], bh[ntp][1]);
                    mma16816(d[mt][2 * ntp + 1], al2[mt], bh[ntp][2], bh[ntp][3]);
                }
        }

        // Epilogue: C frag (c0,c1)->(row, col..col+1), (c2,c3)->(row+8, ...)
        #pragma unroll
        for (int mt = 0; mt < 2; mt++) {
            int row = n0 + m0w + 16 * mt + (l >> 2);
            float* zp0 = Z + ((size_t)rel * NN + row) * DD;
            float* zp1 = zp0 + 8 * DD;
            if (row < NN) {
                #pragma unroll
                for (int nt = 0; nt < 8; nt++) {
                    int col = n0w + 8 * nt + 2 * (l & 3);
                    *(float2*)(zp0 + col) = make_float2(d[mt][nt][0], d[mt][nt][1]);
                }
            }
            if (row + 8 < NN) {
                #pragma unroll
                for (int nt = 0; nt < 8; nt++) {
                    int col = n0w + 8 * nt + 2 * (l & 3);
                    *(float2*)(zp1 + col) = make_float2(d[mt][nt][2], d[mt][nt][3]);
                }
            }
        }

        if (rel == 0) {
            asm volatile("cp.async.wait_group 0;" ::: "memory");
            __syncthreads();
        }
    }
}

// ---------------- scatter: out[row] += val * Z[rr][col]  (1 warp per edge) ----------------
__global__ void __launch_bounds__(256, 4)
scatter_kernel(const float* __restrict__ Z, const float* __restrict__ ev,
               const int* __restrict__ er, const int* __restrict__ ec,
               float* __restrict__ out, int E, int r0)
{
    int ge = blockIdx.x * 8 + (threadIdx.x >> 5);
    if (ge >= 2 * E) return;
    int lane = threadIdx.x & 31;
    int rr = ge / E;
    int e = ge - rr * E;
    int r = r0 + rr;
    int col = __ldg(ec + r * E + e);
    int row = __ldg(er + r * E + e);
    float val = __ldg(ev + r * E + e);
    float4 v = *(const float4*)(Z + ((size_t)rr * NN + col) * DD + lane * 4);
    v.x *= val; v.y *= val; v.z *= val; v.w *= val;
    float* dst = out + (size_t)row * DD + lane * 4;
    asm volatile("red.global.add.v4.f32 [%0], {%1,%2,%3,%4};"
                 :: "l"(dst), "f"(v.x), "f"(v.y), "f"(v.z), "f"(v.w) : "memory");
}

// ---------------- split fp32 -> bf16 hi/lo, 8 elems/thread (optionally relu) ----------------
__global__ void split_kernel(const float* __restrict__ in, __nv_bfloat16* __restrict__ hi,
                             __nv_bfloat16* __restrict__ lo, int n8, int doRelu)
{
    int i = blockIdx.x * 256 + threadIdx.x;
    if (i >= n8) return;
    const float4* in4 = (const float4*)in + 2 * (size_t)i;
    float4 x0 = in4[0], x1 = in4[1];
    float xs[8] = {x0.x, x0.y, x0.z, x0.w, x1.x, x1.y, x1.z, x1.w};
    __nv_bfloat16 hs[8], ls[8];
    #pragma unroll
    for (int k = 0; k < 8; k++) {
        float x = xs[k];
        if (doRelu) x = fmaxf(x, 0.f);
        __nv_bfloat16 h = __float2bfloat16(x);
        hs[k] = h;
        ls[k] = __float2bfloat16(x - __bfloat162float(h));
    }
    *((uint4*)hi + i) = *(uint4*)hs;
    *((uint4*)lo + i) = *(uint4*)ls;
}

__global__ void zero4_kernel(float4* __restrict__ p, int n) {
    int i = blockIdx.x * 256 + threadIdx.x;
    if (i < n) p[i] = make_float4(0.f, 0.f, 0.f, 0.f);
}

// Final: relu + L2 row-normalize. One warp per row.
__global__ void norm_kernel(const float* __restrict__ in, float* __restrict__ out, int n) {
    int row = blockIdx.x * 8 + (threadIdx.x >> 5);
    int lane = threadIdx.x & 31;
    if (row >= n) return;
    float4 v = *reinterpret_cast<const float4*>(in + (size_t)row * DD + lane * 4);
    v.x = fmaxf(v.x, 0.f); v.y = fmaxf(v.y, 0.f);
    v.z = fmaxf(v.z, 0.f); v.w = fmaxf(v.w, 0.f);
    float s = v.x * v.x + v.y * v.y + v.z * v.z + v.w * v.w;
    #pragma unroll
    for (int o = 16; o; o >>= 1) s += __shfl_xor_sync(0xffffffffu, s, o);
    float sc = 1.f / fmaxf(sqrtf(s), 1e-12f);
    v.x *= sc; v.y *= sc; v.z *= sc; v.w *= sc;
    *reinterpret_cast<float4*>(out + (size_t)row * DD + lane * 4) = v;
}

extern "C" void kernel_launch(void* const* d_in, const int* in_sizes, int n_in,
                              void* d_out, int out_size) {
    const float* ent = (const float*)d_in[0];   // [N, D]
    const float* Tm  = (const float*)d_in[1];   // [R, D, D]
    const float* ev  = (const float*)d_in[2];   // [R, E]
    const int*   er  = (const int*)d_in[3];     // [R, E]
    const int*   ec  = (const int*)d_in[4];     // [R, E]
    float* out = (float*)d_out;

    const int E = in_sizes[2] / RR;

    float *out0, *out1, *Z;
    __nv_bfloat16 *ehi, *elo, *Thi, *Tlo;
    cudaGetSymbolAddress((void**)&out0, g_out0);
    cudaGetSymbolAddress((void**)&out1, g_out1);
    cudaGetSymbolAddress((void**)&Z, g_Z);
    cudaGetSymbolAddress((void**)&ehi, g_ehi);
    cudaGetSymbolAddress((void**)&elo, g_elo);
    cudaGetSymbolAddress((void**)&Thi, g_Thi);
    cudaGetSymbolAddress((void**)&Tlo, g_Tlo);

    cudaFuncSetAttribute(gemm2_kernel, cudaFuncAttributeMaxDynamicSharedMemorySize, SMEM_SZ2);

    const int nE = NN * DD;                 // 6.4M
    const int nT = RR * DD * DD;
    const int rowTiles = (NN + 127) / 128;  // 391
    const int sgrid = (2 * E + 7) / 8;

    // Split relation matrices.
    split_kernel<<<(nT / 8 + 255) / 256, 256>>>(Tm, Thi, Tlo, nT / 8, 0);

    // ---- layer 1 ----
    split_kernel<<<(nE / 8 + 255) / 256, 256>>>(ent, ehi, elo, nE / 8, 0);
    zero4_kernel<<<(nE / 4 + 255) / 256, 256>>>((float4*)out0, nE / 4);
    for (int r0 = 0; r0 < RR; r0 += 2) {
        gemm2_kernel<<<rowTiles, 256, SMEM_SZ2>>>(ehi, elo, Thi, Tlo, Z, r0);
        scatter_kernel<<<sgrid, 256>>>(Z, ev, er, ec, out0, E, r0);
    }

    // ---- layer 2 ----
    split_kernel<<<(nE / 8 + 255) / 256, 256>>>(out0, ehi, elo, nE / 8, 1);
    zero4_kernel<<<(nE / 4 + 255) / 256, 256>>>((float4*)out1, nE / 4);
    for (int r0 = 0; r0 < RR; r0 += 2) {
        gemm2_kernel<<<rowTiles, 256, SMEM_SZ2>>>(ehi, elo, Thi, Tlo, Z, r0);
        scatter_kernel<<<sgrid, 256>>>(Z, ev, er, ec, out1, E, r0);
    }

    norm_kernel<<<(NN + 7) / 8, 256>>>(out1, out, NN);
}